// round 15
// baseline (speedup 1.0000x reference)
#include <cuda_runtime.h>
#include <cuda_fp16.h>
#include <math.h>
#include <stdint.h>

#define H 1024
#define E 8
#define T_TOK 8192
#define MAXR 16384
#define NITER 32            // single fp16 pass, 32 k-chunks (BK=32)
#define SMSTRIDE 80         // bytes per SMEM row (64B data + 16B pad, ldmatrix conflict-free)
#define STAGES 3

// ---- device-global scratch (allocation-free rule) ----
__device__ int   d_counts[E];
__device__ int   d_tok[E * MAXR];
__device__ float d_gate[E * MAXR];
__device__ __half g_xh[(size_t)T_TOK * H];
__device__ __half g_wh[(size_t)E * H * H];   // transposed: [e][n][k]

__device__ __forceinline__ unsigned smem_u32(const void* p) {
    return (unsigned)__cvta_generic_to_shared(p);
}
__device__ __forceinline__ void ldmatrix_x4(unsigned r[4], unsigned addr) {
    asm volatile("ldmatrix.sync.aligned.m8n8.x4.shared.b16 {%0,%1,%2,%3}, [%4];"
                 : "=r"(r[0]), "=r"(r[1]), "=r"(r[2]), "=r"(r[3]) : "r"(addr));
}
__device__ __forceinline__ void mma_fp16(float d[4], const unsigned a[4],
                                         unsigned b0, unsigned b1) {
    asm volatile(
        "mma.sync.aligned.m16n8k16.row.col.f32.f16.f16.f32 "
        "{%0,%1,%2,%3}, {%4,%5,%6,%7}, {%8,%9}, {%0,%1,%2,%3};"
        : "+f"(d[0]), "+f"(d[1]), "+f"(d[2]), "+f"(d[3])
        : "r"(a[0]), "r"(a[1]), "r"(a[2]), "r"(a[3]), "r"(b0), "r"(b1));
}
__device__ __forceinline__ void cp16(unsigned dst, const void* src, int src_bytes) {
    asm volatile("cp.async.cg.shared.global [%0], [%1], 16, %2;"
                 :: "r"(dst), "l"(src), "r"(src_bytes) : "memory");
}
__device__ __forceinline__ void cp_commit() {
    asm volatile("cp.async.commit_group;" ::: "memory");
}
__device__ __forceinline__ void cp_wait1() {
    asm volatile("cp.async.wait_group 1;" ::: "memory");
}

// ---------------- convert_we (+ zero counts + zero out) ----------------
// We[e][k][n] fp32 -> g_wh[e][n][k] fp16 (tiled transpose, half2 stores).
// Each block also zeroes its 4KB slice of out (replaces the memset node).
__global__ void convert_we_k(const float* __restrict__ We, float* __restrict__ out) {
    __shared__ float t[32][33];           // t[k][n]
    const int tx = threadIdx.x, ty = threadIdx.y;
    const int tid = ty * 32 + tx;
    if (blockIdx.x == 0 && blockIdx.y == 0 && blockIdx.z == 0 &&
        ty == 0 && tx < E)
        d_counts[tx] = 0;

    // zero this block's slice of out (8192 blocks x 1024 floats = full output)
    const int blockflat = (blockIdx.z * 32 + blockIdx.y) * 32 + blockIdx.x;
    *(float4*)&out[(size_t)blockflat * 1024 + tid * 4] = make_float4(0.f, 0.f, 0.f, 0.f);

    const int e = blockIdx.z, n0 = blockIdx.x * 32, k0 = blockIdx.y * 32;
    const float* W = We + ((size_t)e << 20);
#pragma unroll
    for (int j = 0; j < 4; j++) {
        int k = ty + j * 8;
        t[k][tx] = W[(size_t)(k0 + k) * H + n0 + tx];
    }
    __syncthreads();
    // vectorized transposed store: 512 half2 words, 2 per thread, coalesced in kw
#pragma unroll
    for (int rep = 0; rep < 2; rep++) {
        int id = tid + rep * 256;
        int n  = id >> 4;          // 0..31
        int kw = id & 15;          // half2 index within 32 k
        __half2 v = __floats2half2_rn(t[2 * kw][n], t[2 * kw + 1][n]);
        *(__half2*)&g_wh[((size_t)e << 20) + (size_t)(n0 + n) * H + k0 + 2 * kw] = v;
    }
}

// ---------------- fused router + x->fp16 convert (float4 MLP) ----------------
__global__ void router_k(const float* __restrict__ x, const float* __restrict__ Wg) {
    const int gwarp = (blockIdx.x * blockDim.x + threadIdx.x) >> 5;
    const int lane  = threadIdx.x & 31;
    if (gwarp >= T_TOK) return;
    const float4* xr4 = (const float4*)(x + (size_t)gwarp * H);
    const float4* Wg4 = (const float4*)Wg;
    __half* xh = g_xh + (size_t)gwarp * H;

    float acc[E];
#pragma unroll
    for (int e = 0; e < E; e++) acc[e] = 0.f;

#pragma unroll
    for (int i = 0; i < 8; i++) {
        const int idx = i * 32 + lane;        // float4 index within row (0..255)
        float4 xv = __ldg(&xr4[idx]);
        const int h = idx * 4;
        __half hh[4] = {__float2half_rn(xv.x), __float2half_rn(xv.y),
                        __float2half_rn(xv.z), __float2half_rn(xv.w)};
        *(uint2*)&xh[h] = *(uint2*)hh;
        const float xs[4] = {xv.x, xv.y, xv.z, xv.w};
#pragma unroll
        for (int c = 0; c < 4; c++) {
            float4 w0 = __ldg(&Wg4[(h + c) * 2]);
            float4 w1 = __ldg(&Wg4[(h + c) * 2 + 1]);
            acc[0] = fmaf(xs[c], w0.x, acc[0]); acc[1] = fmaf(xs[c], w0.y, acc[1]);
            acc[2] = fmaf(xs[c], w0.z, acc[2]); acc[3] = fmaf(xs[c], w0.w, acc[3]);
            acc[4] = fmaf(xs[c], w1.x, acc[4]); acc[5] = fmaf(xs[c], w1.y, acc[5]);
            acc[6] = fmaf(xs[c], w1.z, acc[6]); acc[7] = fmaf(xs[c], w1.w, acc[7]);
        }
    }
#pragma unroll
    for (int e = 0; e < E; e++)
#pragma unroll
        for (int o = 16; o > 0; o >>= 1)
            acc[e] += __shfl_xor_sync(0xffffffffu, acc[e], o);

    if (lane == 0) {
        int i0 = 0;
#pragma unroll
        for (int e = 1; e < E; e++) if (acc[e] > acc[i0]) i0 = e;
        int i1 = (i0 == 0) ? 1 : 0;
#pragma unroll
        for (int e = 0; e < E; e++) {
            if (e == i0) continue;
            if (acc[e] > acc[i1]) i1 = e;
        }
        float d  = expf(acc[i1] - acc[i0]);
        float s  = 1.f + d;
        int p0 = atomicAdd(&d_counts[i0], 1);
        d_tok[i0 * MAXR + p0]  = gwarp;
        d_gate[i0 * MAXR + p0] = 1.f / s;
        int p1 = atomicAdd(&d_counts[i1], 1);
        d_tok[i1 * MAXR + p1]  = gwarp;
        d_gate[i1 * MAXR + p1] = d / s;
    }
}

// ---------------- HMMA gathered expert GEMM (fp16, cp.async 3-stage) ----------------
// (byte-identical mainloop/epilogue to the 188.6us round-10 kernel)
__global__ __launch_bounds__(256)
void expert_gemm_hmma(const float* __restrict__ be, float* __restrict__ out) {
    const int e   = blockIdx.z;
    const int cnt = d_counts[e];
    const int m0  = blockIdx.y * 128;
    if (m0 >= cnt) return;
    const int n0  = blockIdx.x * 128;

    __shared__ __align__(16) unsigned char smA[STAGES][128 * SMSTRIDE];
    __shared__ __align__(16) unsigned char smB[STAGES][128 * SMSTRIDE];
    __shared__ int   toks[128];
    __shared__ float gts[128];

    const int tid  = threadIdx.x;
    const int lane = tid & 31;
    const int wid  = tid >> 5;
    const int wy   = wid & 3;    // M dim: 4 warps x 32 rows
    const int wx   = wid >> 2;   // N dim: 2 warps x 64 cols

    if (tid < 128) {
        int r = m0 + tid;
        toks[tid] = (r < cnt) ? d_tok[e * MAXR + r]  : -1;
        gts[tid]  = (r < cnt) ? d_gate[e * MAXR + r] : 0.f;
    }
    __syncthreads();

    const int ar0 = tid >> 2,        ac0 = tid & 3;
    const int ar1 = ar0 + 64;
    const int t0 = toks[ar0], t1 = toks[ar1];
    const __half* pa0 = g_xh + (size_t)(t0 < 0 ? 0 : t0) * H + ac0 * 8;
    const __half* pa1 = g_xh + (size_t)(t1 < 0 ? 0 : t1) * H + ac0 * 8;
    const __half* pb0 = g_wh + ((size_t)e << 20) + (size_t)(n0 + ar0) * H + ac0 * 8;
    const __half* pb1 = g_wh + ((size_t)e << 20) + (size_t)(n0 + ar1) * H + ac0 * 8;
    const int sz0 = (t0 >= 0) ? 16 : 0;
    const int sz1 = (t1 >= 0) ? 16 : 0;
    const unsigned so0 = ar0 * SMSTRIDE + ac0 * 16;
    const unsigned so1 = ar1 * SMSTRIDE + ac0 * 16;

    float acc[2][4][2][4];
#pragma unroll
    for (int i = 0; i < 2; i++)
#pragma unroll
        for (int j = 0; j < 4; j++)
#pragma unroll
            for (int s = 0; s < 2; s++)
#pragma unroll
                for (int q = 0; q < 4; q++) acc[i][j][s][q] = 0.f;

    const unsigned aBase = smem_u32(smA[0]);
    const unsigned bBase = smem_u32(smB[0]);
    const unsigned bufSz = 128 * SMSTRIDE;
    const unsigned lmRow = lane & 15;
    const unsigned lmHi  = lane >> 4;

    auto issue = [&](int stage, int it) {
        const int kk = it * 32;
        const unsigned off = stage * bufSz;
        cp16(aBase + off + so0, pa0 + kk, sz0);
        cp16(aBase + off + so1, pa1 + kk, sz1);
        cp16(bBase + off + so0, pb0 + kk, 16);
        cp16(bBase + off + so1, pb1 + kk, 16);
    };
    auto compute = [&](int stage) {
        const unsigned ab = aBase + stage * bufSz;
        const unsigned bb = bBase + stage * bufSz;
#pragma unroll
        for (int ks = 0; ks < 2; ks++) {
            unsigned a[2][4];
#pragma unroll
            for (int i = 0; i < 2; i++)
                ldmatrix_x4(a[i], ab + (wy * 32 + i * 16 + lmRow) * SMSTRIDE
                                     + (ks * 2 + lmHi) * 16);
#pragma unroll
            for (int j = 0; j < 4; j++) {
                unsigned b[4];
                ldmatrix_x4(b, bb + (wx * 64 + j * 16 + lmRow) * SMSTRIDE
                                  + (ks * 2 + lmHi) * 16);
#pragma unroll
                for (int i = 0; i < 2; i++) {
                    mma_fp16(acc[i][j][0], a[i], b[0], b[2]);
                    mma_fp16(acc[i][j][1], a[i], b[1], b[3]);
                }
            }
        }
    };

    issue(0, 0); cp_commit();
    issue(1, 1); cp_commit();

#pragma unroll 1
    for (int it = 0; it < NITER; it++) {
        cp_wait1();
        __syncthreads();
        compute(it % STAGES);
        if (it + 2 < NITER) issue((it + 2) % STAGES, it + 2);
        cp_commit();
    }

    const int qr = lane >> 2;
    const int qc = lane & 3;
    const float* beE = be + e * H;
#pragma unroll
    for (int i = 0; i < 2; i++) {
        const int rlo = wy * 32 + i * 16 + qr;
        const int rhi = rlo + 8;
        const int tlo = toks[rlo], thi = toks[rhi];
        const float glo = gts[rlo], ghi = gts[rhi];
        float* olo = out + (size_t)(tlo < 0 ? 0 : tlo) * H;
        float* ohi = out + (size_t)(thi < 0 ? 0 : thi) * H;
#pragma unroll
        for (int j = 0; j < 4; j++)
#pragma unroll
            for (int s = 0; s < 2; s++) {
                const int col = n0 + wx * 64 + j * 16 + s * 8 + qc * 2;
                const float b0 = __ldg(&beE[col]);
                const float b1 = __ldg(&beE[col + 1]);
                if (tlo >= 0) {
                    atomicAdd(&olo[col],     glo * (acc[i][j][s][0] + b0));
                    atomicAdd(&olo[col + 1], glo * (acc[i][j][s][1] + b1));
                }
                if (thi >= 0) {
                    atomicAdd(&ohi[col],     ghi * (acc[i][j][s][2] + b0));
                    atomicAdd(&ohi[col + 1], ghi * (acc[i][j][s][3] + b1));
                }
            }
    }
}

extern "C" void kernel_launch(void* const* d_in, const int* in_sizes, int n_in,
                              void* d_out, int out_size) {
    const float* x  = (const float*)d_in[0];   // (4,2048,1024)
    const float* Wg = (const float*)d_in[1];   // (1024, 8)
    const float* We = (const float*)d_in[2];   // (8, 1024, 1024)
    const float* be = (const float*)d_in[3];   // (8, 1024)
    float* out = (float*)d_out;

    convert_we_k<<<dim3(32, 32, E), dim3(32, 8)>>>(We, out);  // zeroes counts + out
    router_k<<<T_TOK / 8, 256>>>(x, Wg);                      // emits g_xh

    // grid: x = n-tile (8), y = m-tile (worst-case 64/expert), z = expert
    expert_gemm_hmma<<<dim3(H / 128, 64, E), 256>>>(be, out);
}

// round 16
// speedup vs baseline: 1.1508x; 1.1508x over previous
#include <cuda_runtime.h>
#include <cuda_fp16.h>
#include <math.h>
#include <stdint.h>

#define H 1024
#define E 8
#define T_TOK 8192
#define MAXR 16384
#define NITER 32            // single fp16 pass, 32 k-chunks (BK=32)
#define SMSTRIDE 80         // bytes per SMEM row (64B data + 16B pad, ldmatrix conflict-free)
#define STAGES 3

// ---- device-global scratch (allocation-free rule) ----
__device__ int   d_counts[E];
__device__ int   d_tok[E * MAXR];
__device__ float d_gate[E * MAXR];
__device__ __half g_xh[(size_t)T_TOK * H];
__device__ __half g_wh[(size_t)E * H * H];   // transposed: [e][n][k]

__device__ __forceinline__ unsigned smem_u32(const void* p) {
    return (unsigned)__cvta_generic_to_shared(p);
}
__device__ __forceinline__ void ldmatrix_x4(unsigned r[4], unsigned addr) {
    asm volatile("ldmatrix.sync.aligned.m8n8.x4.shared.b16 {%0,%1,%2,%3}, [%4];"
                 : "=r"(r[0]), "=r"(r[1]), "=r"(r[2]), "=r"(r[3]) : "r"(addr));
}
__device__ __forceinline__ void mma_fp16(float d[4], const unsigned a[4],
                                         unsigned b0, unsigned b1) {
    asm volatile(
        "mma.sync.aligned.m16n8k16.row.col.f32.f16.f16.f32 "
        "{%0,%1,%2,%3}, {%4,%5,%6,%7}, {%8,%9}, {%0,%1,%2,%3};"
        : "+f"(d[0]), "+f"(d[1]), "+f"(d[2]), "+f"(d[3])
        : "r"(a[0]), "r"(a[1]), "r"(a[2]), "r"(a[3]), "r"(b0), "r"(b1));
}
__device__ __forceinline__ void cp16(unsigned dst, const void* src, int src_bytes) {
    asm volatile("cp.async.cg.shared.global [%0], [%1], 16, %2;"
                 :: "r"(dst), "l"(src), "r"(src_bytes) : "memory");
}
__device__ __forceinline__ void cp_commit() {
    asm volatile("cp.async.commit_group;" ::: "memory");
}
__device__ __forceinline__ void cp_wait1() {
    asm volatile("cp.async.wait_group 1;" ::: "memory");
}

// ---------------- convert_we (+ zero counts + zero out) ----------------
// Round-10 convert_we (scalar transposed stores), plus: zero d_counts and
// this block's 4KB slice of out (replaces the cudaMemsetAsync node).
__global__ void convert_we_k(const float* __restrict__ We, float* __restrict__ out) {
    __shared__ float t[32][33];
    const int tx = threadIdx.x, ty = threadIdx.y;
    const int tid = ty * 32 + tx;
    if (blockIdx.x == 0 && blockIdx.y == 0 && blockIdx.z == 0 &&
        ty == 0 && tx < E)
        d_counts[tx] = 0;

    // zero this block's slice of out (8192 blocks x 1024 floats = full 8192x1024 output)
    const int blockflat = (blockIdx.z * 32 + blockIdx.y) * 32 + blockIdx.x;
    *(float4*)&out[(size_t)blockflat * 1024 + tid * 4] = make_float4(0.f, 0.f, 0.f, 0.f);

    const int e = blockIdx.z, n0 = blockIdx.x * 32, k0 = blockIdx.y * 32;
    const float* W = We + ((size_t)e << 20);
#pragma unroll
    for (int j = 0; j < 4; j++)
        t[ty + j * 8][tx] = W[(size_t)(k0 + ty + j * 8) * H + n0 + tx];
    __syncthreads();
#pragma unroll
    for (int j = 0; j < 4; j++) {
        size_t o = ((size_t)e << 20) + (size_t)(n0 + ty + j * 8) * H + k0 + tx;
        g_wh[o] = __float2half_rn(t[tx][ty + j * 8]);
    }
}

// ---------------- fused router + x->fp16 convert (round-10 proven version) ----
__global__ void router_k(const float* __restrict__ x, const float* __restrict__ Wg) {
    int gwarp = (blockIdx.x * blockDim.x + threadIdx.x) >> 5;
    int lane  = threadIdx.x & 31;
    if (gwarp >= T_TOK) return;
    const float* xr = x + (size_t)gwarp * H;
    __half* xh = g_xh + (size_t)gwarp * H;

    float acc[E];
#pragma unroll
    for (int e = 0; e < E; e++) acc[e] = 0.f;
#pragma unroll 4
    for (int i = 0; i < H / 32; i++) {
        int h = lane + i * 32;
        float xv = __ldg(&xr[h]);
        xh[h] = __float2half_rn(xv);              // fused convert_x
        float4 w0 = *(const float4*)&Wg[h * E];
        float4 w1 = *(const float4*)&Wg[h * E + 4];
        acc[0] = fmaf(xv, w0.x, acc[0]); acc[1] = fmaf(xv, w0.y, acc[1]);
        acc[2] = fmaf(xv, w0.z, acc[2]); acc[3] = fmaf(xv, w0.w, acc[3]);
        acc[4] = fmaf(xv, w1.x, acc[4]); acc[5] = fmaf(xv, w1.y, acc[5]);
        acc[6] = fmaf(xv, w1.z, acc[6]); acc[7] = fmaf(xv, w1.w, acc[7]);
    }
#pragma unroll
    for (int e = 0; e < E; e++)
#pragma unroll
        for (int o = 16; o > 0; o >>= 1)
            acc[e] += __shfl_xor_sync(0xffffffffu, acc[e], o);

    if (lane == 0) {
        int i0 = 0;
#pragma unroll
        for (int e = 1; e < E; e++) if (acc[e] > acc[i0]) i0 = e;
        int i1 = (i0 == 0) ? 1 : 0;
#pragma unroll
        for (int e = 0; e < E; e++) {
            if (e == i0) continue;
            if (acc[e] > acc[i1]) i1 = e;
        }
        float d  = expf(acc[i1] - acc[i0]);
        float s  = 1.f + d;
        int p0 = atomicAdd(&d_counts[i0], 1);
        d_tok[i0 * MAXR + p0]  = gwarp;
        d_gate[i0 * MAXR + p0] = 1.f / s;
        int p1 = atomicAdd(&d_counts[i1], 1);
        d_tok[i1 * MAXR + p1]  = gwarp;
        d_gate[i1 * MAXR + p1] = d / s;
    }
}

// ---------------- HMMA gathered expert GEMM (fp16, cp.async 3-stage) ----------------
// (byte-identical to the 188.6us round-10 kernel)
__global__ __launch_bounds__(256)
void expert_gemm_hmma(const float* __restrict__ be, float* __restrict__ out) {
    const int e   = blockIdx.z;
    const int cnt = d_counts[e];
    const int m0  = blockIdx.y * 128;
    if (m0 >= cnt) return;
    const int n0  = blockIdx.x * 128;

    __shared__ __align__(16) unsigned char smA[STAGES][128 * SMSTRIDE];
    __shared__ __align__(16) unsigned char smB[STAGES][128 * SMSTRIDE];
    __shared__ int   toks[128];
    __shared__ float gts[128];

    const int tid  = threadIdx.x;
    const int lane = tid & 31;
    const int wid  = tid >> 5;
    const int wy   = wid & 3;    // M dim: 4 warps x 32 rows
    const int wx   = wid >> 2;   // N dim: 2 warps x 64 cols

    if (tid < 128) {
        int r = m0 + tid;
        toks[tid] = (r < cnt) ? d_tok[e * MAXR + r]  : -1;
        gts[tid]  = (r < cnt) ? d_gate[e * MAXR + r] : 0.f;
    }
    __syncthreads();

    const int ar0 = tid >> 2,        ac0 = tid & 3;
    const int ar1 = ar0 + 64;
    const int t0 = toks[ar0], t1 = toks[ar1];
    const __half* pa0 = g_xh + (size_t)(t0 < 0 ? 0 : t0) * H + ac0 * 8;
    const __half* pa1 = g_xh + (size_t)(t1 < 0 ? 0 : t1) * H + ac0 * 8;
    const __half* pb0 = g_wh + ((size_t)e << 20) + (size_t)(n0 + ar0) * H + ac0 * 8;
    const __half* pb1 = g_wh + ((size_t)e << 20) + (size_t)(n0 + ar1) * H + ac0 * 8;
    const int sz0 = (t0 >= 0) ? 16 : 0;
    const int sz1 = (t1 >= 0) ? 16 : 0;
    const unsigned so0 = ar0 * SMSTRIDE + ac0 * 16;
    const unsigned so1 = ar1 * SMSTRIDE + ac0 * 16;

    float acc[2][4][2][4];
#pragma unroll
    for (int i = 0; i < 2; i++)
#pragma unroll
        for (int j = 0; j < 4; j++)
#pragma unroll
            for (int s = 0; s < 2; s++)
#pragma unroll
                for (int q = 0; q < 4; q++) acc[i][j][s][q] = 0.f;

    const unsigned aBase = smem_u32(smA[0]);
    const unsigned bBase = smem_u32(smB[0]);
    const unsigned bufSz = 128 * SMSTRIDE;
    const unsigned lmRow = lane & 15;
    const unsigned lmHi  = lane >> 4;

    auto issue = [&](int stage, int it) {
        const int kk = it * 32;
        const unsigned off = stage * bufSz;
        cp16(aBase + off + so0, pa0 + kk, sz0);
        cp16(aBase + off + so1, pa1 + kk, sz1);
        cp16(bBase + off + so0, pb0 + kk, 16);
        cp16(bBase + off + so1, pb1 + kk, 16);
    };
    auto compute = [&](int stage) {
        const unsigned ab = aBase + stage * bufSz;
        const unsigned bb = bBase + stage * bufSz;
#pragma unroll
        for (int ks = 0; ks < 2; ks++) {
            unsigned a[2][4];
#pragma unroll
            for (int i = 0; i < 2; i++)
                ldmatrix_x4(a[i], ab + (wy * 32 + i * 16 + lmRow) * SMSTRIDE
                                     + (ks * 2 + lmHi) * 16);
#pragma unroll
            for (int j = 0; j < 4; j++) {
                unsigned b[4];
                ldmatrix_x4(b, bb + (wx * 64 + j * 16 + lmRow) * SMSTRIDE
                                  + (ks * 2 + lmHi) * 16);
#pragma unroll
                for (int i = 0; i < 2; i++) {
                    mma_fp16(acc[i][j][0], a[i], b[0], b[2]);
                    mma_fp16(acc[i][j][1], a[i], b[1], b[3]);
                }
            }
        }
    };

    issue(0, 0); cp_commit();
    issue(1, 1); cp_commit();

#pragma unroll 1
    for (int it = 0; it < NITER; it++) {
        cp_wait1();
        __syncthreads();
        compute(it % STAGES);
        if (it + 2 < NITER) issue((it + 2) % STAGES, it + 2);
        cp_commit();
    }

    const int qr = lane >> 2;
    const int qc = lane & 3;
    const float* beE = be + e * H;
#pragma unroll
    for (int i = 0; i < 2; i++) {
        const int rlo = wy * 32 + i * 16 + qr;
        const int rhi = rlo + 8;
        const int tlo = toks[rlo], thi = toks[rhi];
        const float glo = gts[rlo], ghi = gts[rhi];
        float* olo = out + (size_t)(tlo < 0 ? 0 : tlo) * H;
        float* ohi = out + (size_t)(thi < 0 ? 0 : thi) * H;
#pragma unroll
        for (int j = 0; j < 4; j++)
#pragma unroll
            for (int s = 0; s < 2; s++) {
                const int col = n0 + wx * 64 + j * 16 + s * 8 + qc * 2;
                const float b0 = __ldg(&beE[col]);
                const float b1 = __ldg(&beE[col + 1]);
                if (tlo >= 0) {
                    atomicAdd(&olo[col],     glo * (acc[i][j][s][0] + b0));
                    atomicAdd(&olo[col + 1], glo * (acc[i][j][s][1] + b1));
                }
                if (thi >= 0) {
                    atomicAdd(&ohi[col],     ghi * (acc[i][j][s][2] + b0));
                    atomicAdd(&ohi[col + 1], ghi * (acc[i][j][s][3] + b1));
                }
            }
    }
}

extern "C" void kernel_launch(void* const* d_in, const int* in_sizes, int n_in,
                              void* d_out, int out_size) {
    const float* x  = (const float*)d_in[0];   // (4,2048,1024)
    const float* Wg = (const float*)d_in[1];   // (1024, 8)
    const float* We = (const float*)d_in[2];   // (8, 1024, 1024)
    const float* be = (const float*)d_in[3];   // (8, 1024)
    float* out = (float*)d_out;

    convert_we_k<<<dim3(32, 32, E), dim3(32, 8)>>>(We, out);  // zeroes counts + out
    router_k<<<T_TOK / 8, 256>>>(x, Wg);                      // emits g_xh

    // grid: x = n-tile (8), y = m-tile (worst-case 64/expert), z = expert
    expert_gemm_hmma<<<dim3(H / 128, 64, E), 256>>>(be, out);
}